// round 4
// baseline (speedup 1.0000x reference)
#include <cuda_runtime.h>
#include <cstdint>

#define B_ 4
#define T_ 256
#define U_ 64
#define D_ 512
#define H_ 512
#define V_ 1024

// Scratch (allocation-free rule: __device__ globals)
__device__ float g_enc[B_ * T_ * H_];   // 1024 x 512  enc_proj
__device__ float g_dec[B_ * U_ * H_];   // 256  x 512  dec_proj + b1

__device__ __forceinline__ uint32_t f2tf32(float x) {
    uint32_t u;
    asm("cvt.rna.tf32.f32 %0, %1;" : "=r"(u) : "f"(x));
    return u;
}

__device__ __forceinline__ float tanh_fast(float x) {
    float y;
    asm("tanh.approx.f32 %0, %1;" : "=f"(y) : "f"(x));
    return y;
}

__device__ __forceinline__ float gelu_tanh(float x) {
    const float c = 0.7978845608028654f;   // sqrt(2/pi)
    float t = c * (x + 0.044715f * x * x * x);
    return 0.5f * x * (1.0f + tanh_fast(t));
}

__device__ __forceinline__ void mma_tf32(float* acc, uint32_t a0, uint32_t a1,
                                         uint32_t a2, uint32_t a3,
                                         uint32_t b0, uint32_t b1) {
    asm volatile(
        "mma.sync.aligned.m16n8k8.row.col.f32.tf32.tf32.f32 "
        "{%0,%1,%2,%3}, {%4,%5,%6,%7}, {%8,%9}, {%0,%1,%2,%3};"
        : "+f"(acc[0]), "+f"(acc[1]), "+f"(acc[2]), "+f"(acc[3])
        : "r"(a0), "r"(a1), "r"(a2), "r"(a3), "r"(b0), "r"(b1));
}

// ---------------------------------------------------------------------------
// Projection GEMM: out[m,h] = sum_d A[m,d] * W[h*1024 + d] (+ bias[h])
// Tile M=64, N=128, KC=32. which: 0 -> g_enc, 1 -> g_dec.
// ---------------------------------------------------------------------------
__global__ __launch_bounds__(256) void proj_kernel(
    const float* __restrict__ A, const float* __restrict__ W,
    const float* __restrict__ bias, int which)
{
    float* out = which ? g_dec : g_enc;
    __shared__ uint32_t As[64][33];
    __shared__ uint32_t Bs[128][33];

    const int tid  = threadIdx.x;
    const int lane = tid & 31;
    const int w    = tid >> 5;
    const int wm   = w >> 1;      // 0..3 (16 rows each)
    const int wn   = w & 1;       // 0..1 (64 cols each)
    const int m0   = blockIdx.y * 64;
    const int n0   = blockIdx.x * 128;

    float acc[8][4] = {};

    for (int k0 = 0; k0 < D_; k0 += 32) {
        __syncthreads();
        // A tile: 64x32, 8 elems/thread
        {
            int r  = tid >> 2;
            int kb = (tid & 3) * 8;
            const float* src = A + (m0 + r) * D_ + k0 + kb;
            float4 v0 = *(const float4*)(src);
            float4 v1 = *(const float4*)(src + 4);
            As[r][kb + 0] = f2tf32(v0.x); As[r][kb + 1] = f2tf32(v0.y);
            As[r][kb + 2] = f2tf32(v0.z); As[r][kb + 3] = f2tf32(v0.w);
            As[r][kb + 4] = f2tf32(v1.x); As[r][kb + 5] = f2tf32(v1.y);
            As[r][kb + 6] = f2tf32(v1.z); As[r][kb + 7] = f2tf32(v1.w);
        }
        // B tile: 128x32, 16 elems/thread (W row stride = 2*D = 1024)
        {
            int n  = tid >> 1;
            int kb = (tid & 1) * 16;
            const float* src = W + (n0 + n) * (2 * D_) + k0 + kb;
            #pragma unroll
            for (int i = 0; i < 16; i += 4) {
                float4 v = *(const float4*)(src + i);
                Bs[n][kb + i + 0] = f2tf32(v.x);
                Bs[n][kb + i + 1] = f2tf32(v.y);
                Bs[n][kb + i + 2] = f2tf32(v.z);
                Bs[n][kb + i + 3] = f2tf32(v.w);
            }
        }
        __syncthreads();

        #pragma unroll
        for (int kk = 0; kk < 4; kk++) {
            int ar = wm * 16 + (lane >> 2);
            int ac = kk * 8 + (lane & 3);
            uint32_t a0 = As[ar][ac];
            uint32_t a1 = As[ar + 8][ac];
            uint32_t a2 = As[ar][ac + 4];
            uint32_t a3 = As[ar + 8][ac + 4];
            #pragma unroll
            for (int nf = 0; nf < 8; nf++) {
                int br = wn * 64 + nf * 8 + (lane >> 2);
                uint32_t b0 = Bs[br][ac];
                uint32_t b1v = Bs[br][ac + 4];
                mma_tf32(acc[nf], a0, a1, a2, a3, b0, b1v);
            }
        }
    }

    // Epilogue
    int row = m0 + wm * 16 + (lane >> 2);
    #pragma unroll
    for (int nf = 0; nf < 8; nf++) {
        int cg = n0 + wn * 64 + nf * 8 + (lane & 3) * 2;
        float bv0 = bias ? bias[cg]     : 0.0f;
        float bv1 = bias ? bias[cg + 1] : 0.0f;
        out[row * H_ + cg]           = acc[nf][0] + bv0;
        out[row * H_ + cg + 1]       = acc[nf][1] + bv1;
        out[(row + 8) * H_ + cg]     = acc[nf][2] + bv0;
        out[(row + 8) * H_ + cg + 1] = acc[nf][3] + bv1;
    }
}

// ---------------------------------------------------------------------------
// Fused GELU + big GEMM.
// logits[bt*64+u, v] = sum_h gelu(enc[bt,h] + dec[b*64+u,h]) * w2[v,h]
// Tile M=128 (two bt), N=128, KC=32. 8 warps: 4(m: 32 rows) x 2(n: 64 cols).
// ---------------------------------------------------------------------------
__global__ __launch_bounds__(256) void joint_kernel(
    const float* __restrict__ w2, float* __restrict__ out)
{
    __shared__ uint32_t As[128][33];
    __shared__ uint32_t Bs[128][33];

    const int tid  = threadIdx.x;
    const int lane = tid & 31;
    const int w    = tid >> 5;
    const int wm   = w >> 1;      // 0..3, 32 rows each (2 m-frags)
    const int wn   = w & 1;       // 0..1, 64 cols each
    const int yt   = blockIdx.y;  // 0..511
    const int bt0  = yt * 2;
    const int b    = bt0 >> 8;    // /T_
    const int n0   = blockIdx.x * 128;

    float acc[2][8][4] = {};

    for (int k0 = 0; k0 < H_; k0 += 32) {
        __syncthreads();
        // A tile: generate hidden = gelu(enc + dec) in tf32. 16 elems/thread.
        {
            int r  = tid >> 1;           // 0..127
            int kb = (tid & 1) * 16;
            int bt = bt0 + (r >> 6);
            int u  = r & 63;
            const float* ep = g_enc + bt * H_ + k0 + kb;
            const float* dp = g_dec + (b * 64 + u) * H_ + k0 + kb;
            #pragma unroll
            for (int i = 0; i < 16; i += 4) {
                float4 e = *(const float4*)(ep + i);
                float4 d = *(const float4*)(dp + i);
                As[r][kb + i + 0] = f2tf32(gelu_tanh(e.x + d.x));
                As[r][kb + i + 1] = f2tf32(gelu_tanh(e.y + d.y));
                As[r][kb + i + 2] = f2tf32(gelu_tanh(e.z + d.z));
                As[r][kb + i + 3] = f2tf32(gelu_tanh(e.w + d.w));
            }
        }
        // B tile: w2 rows. 16 elems/thread.
        {
            int n  = tid >> 1;
            int kb = (tid & 1) * 16;
            const float* src = w2 + (n0 + n) * H_ + k0 + kb;
            #pragma unroll
            for (int i = 0; i < 16; i += 4) {
                float4 v = *(const float4*)(src + i);
                Bs[n][kb + i + 0] = f2tf32(v.x);
                Bs[n][kb + i + 1] = f2tf32(v.y);
                Bs[n][kb + i + 2] = f2tf32(v.z);
                Bs[n][kb + i + 3] = f2tf32(v.w);
            }
        }
        __syncthreads();

        #pragma unroll
        for (int kk = 0; kk < 4; kk++) {
            int ac = kk * 8 + (lane & 3);
            uint32_t bb[8][2];
            #pragma unroll
            for (int nf = 0; nf < 8; nf++) {
                int br = wn * 64 + nf * 8 + (lane >> 2);
                bb[nf][0] = Bs[br][ac];
                bb[nf][1] = Bs[br][ac + 4];
            }
            #pragma unroll
            for (int mf = 0; mf < 2; mf++) {
                int ar = wm * 32 + mf * 16 + (lane >> 2);
                uint32_t a0 = As[ar][ac];
                uint32_t a1 = As[ar + 8][ac];
                uint32_t a2 = As[ar][ac + 4];
                uint32_t a3 = As[ar + 8][ac + 4];
                #pragma unroll
                for (int nf = 0; nf < 8; nf++)
                    mma_tf32(acc[mf][nf], a0, a1, a2, a3, bb[nf][0], bb[nf][1]);
            }
        }
    }

    // Epilogue: out rows are linear (yt*128 + row) since U_ == 64 tiles pack.
    const int rowbase = yt * 128;
    #pragma unroll
    for (int mf = 0; mf < 2; mf++) {
        int r0 = wm * 32 + mf * 16 + (lane >> 2);
        #pragma unroll
        for (int nf = 0; nf < 8; nf++) {
            int cg = n0 + wn * 64 + nf * 8 + (lane & 3) * 2;
            float2 v0 = make_float2(acc[mf][nf][0], acc[mf][nf][1]);
            float2 v1 = make_float2(acc[mf][nf][2], acc[mf][nf][3]);
            *(float2*)(out + (size_t)(rowbase + r0) * V_ + cg)     = v0;
            *(float2*)(out + (size_t)(rowbase + r0 + 8) * V_ + cg) = v1;
        }
    }
}

extern "C" void kernel_launch(void* const* d_in, const int* in_sizes, int n_in,
                              void* d_out, int out_size) {
    const float* enc = (const float*)d_in[0];  // (4,256,512)
    const float* dec = (const float*)d_in[1];  // (4,64,512)
    const float* w1  = (const float*)d_in[2];  // (512,1024)
    const float* b1  = (const float*)d_in[3];  // (512)
    const float* w2  = (const float*)d_in[4];  // (1024,512)
    float* out = (float*)d_out;                // (4,256,64,1024)

    // enc_proj: M=1024 rows, W = w1[:, :512]
    proj_kernel<<<dim3(H_ / 128, (B_ * T_) / 64), 256>>>(enc, w1, nullptr, 0);
    // dec_proj + b1: M=256 rows, W = w1[:, 512:]
    proj_kernel<<<dim3(H_ / 128, (B_ * U_) / 64), 256>>>(dec, w1 + D_, b1, 1);
    // fused gelu + [65536,512]x[512,1024] GEMM
    joint_kernel<<<dim3(V_ / 128, (B_ * T_) / 2), 256>>>(w2, out);
}

// round 7
// speedup vs baseline: 2.6613x; 2.6613x over previous
#include <cuda_runtime.h>
#include <cstdint>

#define B_ 4
#define T_ 256
#define U_ 64
#define D_ 512
#define H_ 512
#define V_ 1024

// ---------------------------------------------------------------------------
// Device-global scratch (allocation-free rule)
// ---------------------------------------------------------------------------
__device__ float g_enc[B_ * T_ * H_];          // 1024 x 512 enc_proj (fp32)
__device__ float g_dec[B_ * U_ * H_];          // 256  x 512 dec_proj + b1 (fp32)
__device__ uint4 g_w2p[4 * 16 * 2048];         // w2 frag-packed (2 MB)
__device__ uint4 g_hA[512 * 16 * 1024];        // hidden frag-packed (134 MB)

__device__ __forceinline__ uint32_t f2tf32(float x) {
    uint32_t u; asm("cvt.rna.tf32.f32 %0, %1;" : "=r"(u) : "f"(x)); return u;
}
__device__ __forceinline__ float gelu_tanh(float x) {
    float t = 0.7978845608028654f * (x + 0.044715f * x * x * x);
    float th; asm("tanh.approx.f32 %0, %1;" : "=f"(th) : "f"(t));
    return 0.5f * x * (1.0f + th);
}
__device__ __forceinline__ uint32_t smem_u32(const void* p) {
    uint32_t a;
    asm("{ .reg .u64 t; cvta.to.shared.u64 t, %1; cvt.u32.u64 %0, t; }" : "=r"(a) : "l"(p));
    return a;
}
__device__ __forceinline__ void mma_tf32(float* acc, uint32_t a0, uint32_t a1,
                                         uint32_t a2, uint32_t a3,
                                         uint32_t b0, uint32_t b1) {
    asm volatile(
        "mma.sync.aligned.m16n8k8.row.col.f32.tf32.tf32.f32 "
        "{%0,%1,%2,%3}, {%4,%5,%6,%7}, {%8,%9}, {%0,%1,%2,%3};"
        : "+f"(acc[0]), "+f"(acc[1]), "+f"(acc[2]), "+f"(acc[3])
        : "r"(a0), "r"(a1), "r"(a2), "r"(a3), "r"(b0), "r"(b1));
}
__device__ __forceinline__ void cp16(uint32_t sdst, const void* gsrc) {
    asm volatile("cp.async.cg.shared.global [%0], [%1], 16;" :: "r"(sdst), "l"(gsrc));
}
__device__ __forceinline__ void cp_commit() {
    asm volatile("cp.async.commit_group;" ::: "memory");
}
template <int N>
__device__ __forceinline__ void cp_wait() {
    asm volatile("cp.async.wait_group %0;" :: "n"(N) : "memory");
}

// ---------------------------------------------------------------------------
// prep_kernel:
//   blocks 0..159  : enc/dec projections (mma.sync tf32, M=32 N=128 tiles)
//   blocks 160..671: w2 -> g_w2p fragment pack (tf32-rounded)
// Packing: g_w2p[((nt*16+ch)*64 + p*4 + ks)*32 + l] =
//   { w2[R][C], w2[R][C+4], w2[R+8][C], w2[R+8][C+4] }  (tf32 bits)
//   with R = nt*256 + p*16 + (l>>2), C = ch*32 + ks*8 + (l&3)
// ---------------------------------------------------------------------------
__global__ __launch_bounds__(256) void prep_kernel(
    const float* __restrict__ enc, const float* __restrict__ dec,
    const float* __restrict__ w1, const float* __restrict__ b1,
    const float* __restrict__ w2)
{
    const int bid = blockIdx.x;
    const int tid = threadIdx.x;

    if (bid >= 160) {   // ---- w2 fragment pack ----
        int t  = (bid - 160) * 256 + tid;       // 0..131071
        int l  = t & 31;
        int ks = (t >> 5) & 3;
        int p  = (t >> 7) & 15;
        int ch = (t >> 11) & 15;
        int nt = t >> 15;
        int R  = nt * 256 + p * 16 + (l >> 2);
        int C  = ch * 32 + ks * 8 + (l & 3);
        uint4 q;
        q.x = f2tf32(w2[(size_t)R * H_ + C]);
        q.y = f2tf32(w2[(size_t)R * H_ + C + 4]);
        q.z = f2tf32(w2[(size_t)(R + 8) * H_ + C]);
        q.w = f2tf32(w2[(size_t)(R + 8) * H_ + C + 4]);
        g_w2p[((nt * 16 + ch) * 64 + p * 4 + ks) * 32 + l] = q;
        return;
    }

    // ---- projection: out[m,h] = sum_d A[m,d]*W[h*1024+d] (+bias) ----
    const int ng = bid & 3;
    const int my = bid >> 2;          // 0..39
    const bool is_dec = (my >= 32);
    const float* A = is_dec ? dec : enc;
    const float* W = is_dec ? (w1 + D_) : w1;
    float* out     = is_dec ? g_dec : g_enc;
    const int m0   = (is_dec ? (my - 32) : my) * 32;
    const int n0   = ng * 128;

    __shared__ uint32_t As[32][33];
    __shared__ uint32_t Bs[128][33];

    const int lane = tid & 31;
    const int w    = tid >> 5;
    const int wm   = w >> 2;          // 0..1 (16 rows)
    const int wn   = w & 3;           // 0..3 (32 cols)
    float acc[4][4] = {};

    for (int k0 = 0; k0 < D_; k0 += 32) {
        __syncthreads();
        {   // A: 32x32
            int r = tid >> 3, kb = (tid & 7) * 4;
            float4 v = *(const float4*)(A + (size_t)(m0 + r) * D_ + k0 + kb);
            As[r][kb+0]=f2tf32(v.x); As[r][kb+1]=f2tf32(v.y);
            As[r][kb+2]=f2tf32(v.z); As[r][kb+3]=f2tf32(v.w);
        }
        {   // B: 128x32 (W row stride 1024)
            int n = tid >> 1, kb = (tid & 1) * 16;
            const float* src = W + (size_t)(n0 + n) * (2 * D_) + k0 + kb;
            #pragma unroll
            for (int i = 0; i < 16; i += 4) {
                float4 v = *(const float4*)(src + i);
                Bs[n][kb+i+0]=f2tf32(v.x); Bs[n][kb+i+1]=f2tf32(v.y);
                Bs[n][kb+i+2]=f2tf32(v.z); Bs[n][kb+i+3]=f2tf32(v.w);
            }
        }
        __syncthreads();
        #pragma unroll
        for (int kk = 0; kk < 4; kk++) {
            int ar = wm * 16 + (lane >> 2);
            int ac = kk * 8 + (lane & 3);
            uint32_t a0 = As[ar][ac], a1 = As[ar+8][ac];
            uint32_t a2 = As[ar][ac+4], a3 = As[ar+8][ac+4];
            #pragma unroll
            for (int nf = 0; nf < 4; nf++) {
                int br = wn * 32 + nf * 8 + (lane >> 2);
                mma_tf32(acc[nf], a0, a1, a2, a3, Bs[br][ac], Bs[br][ac+4]);
            }
        }
    }
    int row = m0 + wm * 16 + (lane >> 2);
    #pragma unroll
    for (int nf = 0; nf < 4; nf++) {
        int cg = n0 + wn * 32 + nf * 8 + (lane & 3) * 2;
        float bv0 = is_dec ? b1[cg]     : 0.0f;
        float bv1 = is_dec ? b1[cg + 1] : 0.0f;
        out[(size_t)row * H_ + cg]           = acc[nf][0] + bv0;
        out[(size_t)row * H_ + cg + 1]       = acc[nf][1] + bv1;
        out[(size_t)(row + 8) * H_ + cg]     = acc[nf][2] + bv0;
        out[(size_t)(row + 8) * H_ + cg + 1] = acc[nf][3] + bv1;
    }
}

// ---------------------------------------------------------------------------
// hidden_kernel: materialize gelu(enc+dec) ONCE, in A-fragment order.
// g_hA[((mt*16+ch)*32 + mb*4+ks)*32 + l] =
//   { h(r,c), h(r+8,c), h(r,c+4), h(r+8,c+4) } tf32 bits,
//   r = mt*128 + mb*16 + (l>>2)  (global row), c = ch*32 + ks*8 + (l&3)
// Thread <-> (mt, mb, ks, l); loops over ch (16). Writes: STG.128 coalesced.
// ---------------------------------------------------------------------------
__global__ __launch_bounds__(256) void hidden_kernel()
{
    int id = blockIdx.x * 256 + threadIdx.x;    // 0..524287
    int mt = id >> 10;
    int rest = id & 1023;
    int mb = rest >> 7;
    int ks = (rest >> 5) & 3;
    int l  = rest & 31;

    int rl  = mb * 16 + (l >> 2);
    int g   = mt * 128 + rl;        // global row 0..65535
    int bt  = g >> 6;               // enc row
    int u   = g & 63;
    int bat = g >> 14;              // batch

    const float* ep  = g_enc + (size_t)bt * H_;
    const float* dp0 = g_dec + (size_t)(bat * 64 + u) * H_;
    const float* dp1 = dp0 + 8 * H_;

    #pragma unroll 4
    for (int ch = 0; ch < 16; ch++) {
        int C = ch * 32 + ks * 8 + (l & 3);
        float e0 = ep[C],      e1 = ep[C + 4];
        float d00 = dp0[C],    d01 = dp0[C + 4];
        float d10 = dp1[C],    d11 = dp1[C + 4];
        uint4 q;
        q.x = f2tf32(gelu_tanh(e0 + d00));
        q.y = f2tf32(gelu_tanh(e0 + d10));
        q.z = f2tf32(gelu_tanh(e1 + d01));
        q.w = f2tf32(gelu_tanh(e1 + d11));
        g_hA[((size_t)(mt * 16 + ch) * 32 + mb * 4 + ks) * 32 + l] = q;
    }
}

// ---------------------------------------------------------------------------
// gemm_kernel: C[128 x 256 tile] = A_frag @ B_frag^T, tf32 mma.sync,
// cp.async double-buffered 32-k chunks, frag loads are single LDS.128.
// 8 warps, warp tile 64x64 (acc 4mb x 8n8 x 4).
// ---------------------------------------------------------------------------
#define CHUNK_A_BYTES 16384
#define CHUNK_B_BYTES 32768
#define STAGE_BYTES   (CHUNK_A_BYTES + CHUNK_B_BYTES)   // 49152
#define SMEM_GEMM     (2 * STAGE_BYTES)                 // 98304

__global__ __launch_bounds__(256) void gemm_kernel(float* __restrict__ out)
{
    extern __shared__ char smem[];
    const uint32_t sbase = smem_u32(smem);
    const int tid  = threadIdx.x;
    const int lane = tid & 31;
    const int w    = tid >> 5;
    const int wm   = w >> 2;          // 0..1 (64 rows)
    const int wn   = w & 3;           // 0..3 (64 cols)
    const int nt   = blockIdx.x;      // 0..3   (256 cols each)
    const int mt   = blockIdx.y;      // 0..511 (128 rows each)

    const uint4* gA = g_hA  + (size_t)mt * 16 * 1024;
    const uint4* gB = g_w2p + (size_t)nt * 16 * 2048;

    float acc[4][8][4] = {};

    // prologue: chunk 0 -> stage 0
    {
        uint32_t dA = sbase + tid * 16;
        const uint4* sA = gA + tid;
        #pragma unroll
        for (int i = 0; i < 4; i++) cp16(dA + i * 4096, sA + i * 256);
        uint32_t dB = sbase + CHUNK_A_BYTES + tid * 16;
        const uint4* sB = gB + tid;
        #pragma unroll
        for (int i = 0; i < 8; i++) cp16(dB + i * 4096, sB + i * 256);
        cp_commit();
    }

    for (int c = 0; c < 16; c++) {
        const int s = c & 1;
        if (c < 15) {
            const int sn = s ^ 1;
            uint32_t dA = sbase + sn * STAGE_BYTES + tid * 16;
            const uint4* pA = gA + (c + 1) * 1024 + tid;
            #pragma unroll
            for (int i = 0; i < 4; i++) cp16(dA + i * 4096, pA + i * 256);
            uint32_t dB = sbase + sn * STAGE_BYTES + CHUNK_A_BYTES + tid * 16;
            const uint4* pB = gB + (c + 1) * 2048 + tid;
            #pragma unroll
            for (int i = 0; i < 8; i++) cp16(dB + i * 4096, pB + i * 256);
            cp_commit();
            cp_wait<1>();
        } else {
            cp_wait<0>();
        }
        __syncthreads();

        const uint4* sA = (const uint4*)(smem + s * STAGE_BYTES);
        const uint4* sB = (const uint4*)(smem + s * STAGE_BYTES + CHUNK_A_BYTES);

        #pragma unroll
        for (int ks = 0; ks < 4; ks++) {
            uint4 af[4], bf[4];
            #pragma unroll
            for (int mb = 0; mb < 4; mb++)
                af[mb] = sA[((wm * 4 + mb) * 4 + ks) * 32 + lane];
            #pragma unroll
            for (int pp = 0; pp < 4; pp++)
                bf[pp] = sB[((wn * 4 + pp) * 4 + ks) * 32 + lane];
            #pragma unroll
            for (int mb = 0; mb < 4; mb++) {
                #pragma unroll
                for (int pp = 0; pp < 4; pp++) {
                    mma_tf32(acc[mb][2*pp],   af[mb].x, af[mb].y, af[mb].z, af[mb].w,
                             bf[pp].x, bf[pp].y);
                    mma_tf32(acc[mb][2*pp+1], af[mb].x, af[mb].y, af[mb].z, af[mb].w,
                             bf[pp].z, bf[pp].w);
                }
            }
        }
        __syncthreads();
    }

    // epilogue: pairwise STG.64, full 32B sectors per 4 lanes
    #pragma unroll
    for (int mb = 0; mb < 4; mb++) {
        size_t r = (size_t)mt * 128 + wm * 64 + mb * 16 + (lane >> 2);
        #pragma unroll
        for (int n8 = 0; n8 < 8; n8++) {
            int cg = nt * 256 + wn * 64 + n8 * 8 + (lane & 3) * 2;
            *(float2*)(out + r * V_ + cg) =
                make_float2(acc[mb][n8][0], acc[mb][n8][1]);
            *(float2*)(out + (r + 8) * V_ + cg) =
                make_float2(acc[mb][n8][2], acc[mb][n8][3]);
        }
    }
}

extern "C" void kernel_launch(void* const* d_in, const int* in_sizes, int n_in,
                              void* d_out, int out_size) {
    const float* enc = (const float*)d_in[0];
    const float* dec = (const float*)d_in[1];
    const float* w1  = (const float*)d_in[2];
    const float* b1  = (const float*)d_in[3];
    const float* w2  = (const float*)d_in[4];
    float* out = (float*)d_out;

    cudaFuncSetAttribute(gemm_kernel, cudaFuncAttributeMaxDynamicSharedMemorySize,
                         SMEM_GEMM);
    prep_kernel<<<672, 256>>>(enc, dec, w1, b1, w2);
    hidden_kernel<<<2048, 256>>>();
    gemm_kernel<<<dim3(4, 512), 256, SMEM_GEMM>>>(out);
}

// round 8
// speedup vs baseline: 4.2650x; 1.6026x over previous
#include <cuda_runtime.h>
#include <cuda_fp16.h>
#include <cstdint>

#define B_ 4
#define T_ 256
#define U_ 64
#define D_ 512
#define H_ 512
#define V_ 1024

// ---------------------------------------------------------------------------
// Device-global scratch (allocation-free rule)
// ---------------------------------------------------------------------------
__device__ float g_enc[B_ * T_ * H_];          // 1024 x 512 enc_proj (fp32)
__device__ float g_dec[B_ * U_ * H_];          // 256  x 512 dec_proj + b1 (fp32)
__device__ uint4 g_w2p[4 * 16 * 1024];         // w2 fp16 frag-packed (1 MB)
__device__ uint4 g_hA[512 * 16 * 512];         // hidden fp16 frag-packed (67 MB)

__device__ __forceinline__ uint32_t f2tf32(float x) {
    uint32_t u; asm("cvt.rna.tf32.f32 %0, %1;" : "=r"(u) : "f"(x)); return u;
}
__device__ __forceinline__ uint32_t packh2(float a, float b) {
    __half2 h = __floats2half2_rn(a, b);
    return *reinterpret_cast<uint32_t*>(&h);
}
__device__ __forceinline__ float gelu_tanh(float x) {
    float t = 0.7978845608028654f * (x + 0.044715f * x * x * x);
    float th; asm("tanh.approx.f32 %0, %1;" : "=f"(th) : "f"(t));
    return 0.5f * x * (1.0f + th);
}
__device__ __forceinline__ uint32_t smem_u32(const void* p) {
    uint32_t a;
    asm("{ .reg .u64 t; cvta.to.shared.u64 t, %1; cvt.u32.u64 %0, t; }" : "=r"(a) : "l"(p));
    return a;
}
__device__ __forceinline__ void mma_tf32(float* acc, uint32_t a0, uint32_t a1,
                                         uint32_t a2, uint32_t a3,
                                         uint32_t b0, uint32_t b1) {
    asm volatile(
        "mma.sync.aligned.m16n8k8.row.col.f32.tf32.tf32.f32 "
        "{%0,%1,%2,%3}, {%4,%5,%6,%7}, {%8,%9}, {%0,%1,%2,%3};"
        : "+f"(acc[0]), "+f"(acc[1]), "+f"(acc[2]), "+f"(acc[3])
        : "r"(a0), "r"(a1), "r"(a2), "r"(a3), "r"(b0), "r"(b1));
}
__device__ __forceinline__ void mma_f16(float* acc, uint32_t a0, uint32_t a1,
                                        uint32_t a2, uint32_t a3,
                                        uint32_t b0, uint32_t b1) {
    asm volatile(
        "mma.sync.aligned.m16n8k16.row.col.f32.f16.f16.f32 "
        "{%0,%1,%2,%3}, {%4,%5,%6,%7}, {%8,%9}, {%0,%1,%2,%3};"
        : "+f"(acc[0]), "+f"(acc[1]), "+f"(acc[2]), "+f"(acc[3])
        : "r"(a0), "r"(a1), "r"(a2), "r"(a3), "r"(b0), "r"(b1));
}
__device__ __forceinline__ void cp16(uint32_t sdst, const void* gsrc) {
    asm volatile("cp.async.cg.shared.global [%0], [%1], 16;" :: "r"(sdst), "l"(gsrc));
}
__device__ __forceinline__ void cp_commit() {
    asm volatile("cp.async.commit_group;" ::: "memory");
}
template <int N>
__device__ __forceinline__ void cp_wait() {
    asm volatile("cp.async.wait_group %0;" :: "n"(N) : "memory");
}

// ---------------------------------------------------------------------------
// prep_kernel:
//   blocks 0..159  : enc/dec projections (tf32 mma, M=32 N=128, K=64 chunks,
//                    cp.async double-buffered)
//   blocks 160..415: w2 -> g_w2p fp16 fragment pack (m16n8k16 B layout)
//     g_w2p[((nt*16+ch)*32 + p)*32 + l] = uint4 {b0(ks0), b1(ks0), b0(ks1), b1(ks1)}
//     n = nt*256 + p*8 + (l>>2), c0 = ch*32 + (l&3)*2
// ---------------------------------------------------------------------------
#define PA_STRIDE 272                 // 68 floats per row (32 rows)
#define PB_STRIDE 272                 // 68 floats per row (128 rows)
#define P_OFF_A   0                   // 2 x 8704
#define P_OFF_B   17408               // 2 x 34816
#define P_SMEM    87040

__global__ __launch_bounds__(256) void prep_kernel(
    const float* __restrict__ enc, const float* __restrict__ dec,
    const float* __restrict__ w1, const float* __restrict__ b1,
    const float* __restrict__ w2)
{
    const int bid = blockIdx.x;
    const int tid = threadIdx.x;

    if (bid >= 160) {   // ---- w2 fp16 fragment pack ----
        int t  = (bid - 160) * 256 + tid;       // 0..65535
        int l  = t & 31;
        int p  = (t >> 5) & 31;
        int ch = (t >> 10) & 15;
        int nt = t >> 14;
        int n  = nt * 256 + p * 8 + (l >> 2);
        int c0 = ch * 32 + (l & 3) * 2;
        const float* r = w2 + (size_t)n * H_;
        float2 v0 = *(const float2*)(r + c0);
        float2 v1 = *(const float2*)(r + c0 + 8);
        float2 v2 = *(const float2*)(r + c0 + 16);
        float2 v3 = *(const float2*)(r + c0 + 24);
        uint4 q;
        q.x = packh2(v0.x, v0.y);
        q.y = packh2(v1.x, v1.y);
        q.z = packh2(v2.x, v2.y);
        q.w = packh2(v3.x, v3.y);
        g_w2p[((size_t)(nt * 16 + ch) * 32 + p) * 32 + l] = q;
        return;
    }

    // ---- projection: out[m,h] = sum_d A[m,d]*W[h*1024+d] (+bias) ----
    extern __shared__ char psm[];
    const uint32_t sbase = smem_u32(psm);

    const int ng = bid & 3;
    const int my = bid >> 2;          // 0..39
    const bool is_dec = (my >= 32);
    const float* A = is_dec ? dec : enc;
    const float* W = is_dec ? (w1 + D_) : w1;
    float* out     = is_dec ? g_dec : g_enc;
    const int m0   = (is_dec ? (my - 32) : my) * 32;
    const int n0   = ng * 128;

    const int lane = tid & 31;
    const int w    = tid >> 5;
    const int wm   = w >> 2;          // 0..1 (16 rows)
    const int wn   = w & 3;           // 0..3 (32 cols)
    float acc[4][4] = {};

    // prologue: chunk 0 -> stage 0
    {
        if (tid < 128) {   // A: 512 float4 over 128 threads? -> 4 each
            int j = tid;
            #pragma unroll
            for (int i = 0; i < 4; i++, j += 128) {
                int r = j >> 4, seg = j & 15;
                cp16(sbase + P_OFF_A + r * PA_STRIDE + seg * 16,
                     A + (size_t)(m0 + r) * D_ + seg * 4);
            }
        }
        int j = tid;
        #pragma unroll
        for (int i = 0; i < 8; i++, j += 256) {   // B: 2048 float4
            int r = j >> 4, seg = j & 15;
            cp16(sbase + P_OFF_B + r * PB_STRIDE + seg * 16,
                 W + (size_t)(n0 + r) * (2 * D_) + seg * 4);
        }
        cp_commit();
    }

    for (int cc = 0; cc < 8; cc++) {
        const int s = cc & 1;
        if (cc < 7) {
            const int sn = s ^ 1;
            const int k0 = (cc + 1) * 64;
            if (tid < 128) {
                int j = tid;
                #pragma unroll
                for (int i = 0; i < 4; i++, j += 128) {
                    int r = j >> 4, seg = j & 15;
                    cp16(sbase + P_OFF_A + sn * 8704 + r * PA_STRIDE + seg * 16,
                         A + (size_t)(m0 + r) * D_ + k0 + seg * 4);
                }
            }
            int j = tid;
            #pragma unroll
            for (int i = 0; i < 8; i++, j += 256) {
                int r = j >> 4, seg = j & 15;
                cp16(sbase + P_OFF_B + sn * 34816 + r * PB_STRIDE + seg * 16,
                     W + (size_t)(n0 + r) * (2 * D_) + k0 + seg * 4);
            }
            cp_commit();
            cp_wait<1>();
        } else {
            cp_wait<0>();
        }
        __syncthreads();

        const float* Af = (const float*)(psm + P_OFF_A + s * 8704);
        const float* Bf = (const float*)(psm + P_OFF_B + s * 34816);

        #pragma unroll
        for (int kk = 0; kk < 8; kk++) {
            int ar = wm * 16 + (lane >> 2);
            int ac = kk * 8 + (lane & 3);
            uint32_t a0 = f2tf32(Af[ar * 68 + ac]);
            uint32_t a1 = f2tf32(Af[(ar + 8) * 68 + ac]);
            uint32_t a2 = f2tf32(Af[ar * 68 + ac + 4]);
            uint32_t a3 = f2tf32(Af[(ar + 8) * 68 + ac + 4]);
            #pragma unroll
            for (int nf = 0; nf < 4; nf++) {
                int br = wn * 32 + nf * 8 + (lane >> 2);
                uint32_t b0 = f2tf32(Bf[br * 68 + ac]);
                uint32_t b1 = f2tf32(Bf[br * 68 + ac + 4]);
                mma_tf32(acc[nf], a0, a1, a2, a3, b0, b1);
            }
        }
        __syncthreads();
    }

    int row = m0 + wm * 16 + (lane >> 2);
    #pragma unroll
    for (int nf = 0; nf < 4; nf++) {
        int cg = n0 + wn * 32 + nf * 8 + (lane & 3) * 2;
        float bv0 = is_dec ? b1[cg]     : 0.0f;
        float bv1 = is_dec ? b1[cg + 1] : 0.0f;
        out[(size_t)row * H_ + cg]           = acc[nf][0] + bv0;
        out[(size_t)row * H_ + cg + 1]       = acc[nf][1] + bv1;
        out[(size_t)(row + 8) * H_ + cg]     = acc[nf][2] + bv0;
        out[(size_t)(row + 8) * H_ + cg + 1] = acc[nf][3] + bv1;
    }
}

// ---------------------------------------------------------------------------
// hidden_kernel: materialize gelu(enc+dec) once, fp16 A-fragment order.
// Thread <-> (mt, mb, ks, l), loops over ch (16 chunks of k=32).
// g_hA[((mt*16+ch)*16 + mb*2+ks)*32 + l] = uint4 {a0,a1,a2,a3} where
//   r = mt*128 + mb*16 + (l>>2), cb = ch*32 + ks*16 + (l&3)*2
//   a0={h[r][cb],h[r][cb+1]} a1={h[r+8][cb],...} a2={h[r][cb+8],...} a3={h[r+8][cb+8],...}
// ---------------------------------------------------------------------------
__global__ __launch_bounds__(256) void hidden_kernel()
{
    int id = blockIdx.x * 256 + threadIdx.x;    // 0..262143
    int l  = id & 31;
    int ks = (id >> 5) & 1;
    int mb = (id >> 6) & 7;
    int mt = id >> 9;

    int r   = mt * 128 + mb * 16 + (l >> 2);    // global row (r, r+8 same bt)
    int bt  = r >> 6;
    int u   = r & 63;
    int bat = r >> 14;

    const float* ep  = g_enc + (size_t)bt * H_;
    const float* dp0 = g_dec + (size_t)(bat * 64 + u) * H_;
    const float* dp1 = dp0 + 8 * H_;

    #pragma unroll 4
    for (int ch = 0; ch < 16; ch++) {
        int cb = ch * 32 + ks * 16 + (l & 3) * 2;
        float2 e0 = *(const float2*)(ep + cb);
        float2 e1 = *(const float2*)(ep + cb + 8);
        float2 a0 = *(const float2*)(dp0 + cb);
        float2 a1 = *(const float2*)(dp0 + cb + 8);
        float2 c0 = *(const float2*)(dp1 + cb);
        float2 c1 = *(const float2*)(dp1 + cb + 8);
        uint4 q;
        q.x = packh2(gelu_tanh(e0.x + a0.x), gelu_tanh(e0.y + a0.y));
        q.y = packh2(gelu_tanh(e0.x + c0.x), gelu_tanh(e0.y + c0.y));
        q.z = packh2(gelu_tanh(e1.x + a1.x), gelu_tanh(e1.y + a1.y));
        q.w = packh2(gelu_tanh(e1.x + c1.x), gelu_tanh(e1.y + c1.y));
        g_hA[((size_t)(mt * 16 + ch) * 16 + mb * 2 + ks) * 32 + l] = q;
    }
}

// ---------------------------------------------------------------------------
// gemm_kernel: C[128 x 256] tiles, fp16 m16n8k16, cp.async double-buffered
// 32-k chunks (A 8KB + B 16KB per stage). 8 warps, warp tile 64x64.
// ---------------------------------------------------------------------------
#define CHUNK_A 8192
#define CHUNK_B 16384
#define STAGE   (CHUNK_A + CHUNK_B)       // 24576
#define SMEM_GEMM (2 * STAGE)             // 49152

__global__ __launch_bounds__(256) void gemm_kernel(float* __restrict__ out)
{
    extern __shared__ char smem[];
    const uint32_t sbase = smem_u32(smem);
    const int tid  = threadIdx.x;
    const int lane = tid & 31;
    const int w    = tid >> 5;
    const int wm   = w >> 2;          // 0..1 (64 rows)
    const int wn   = w & 3;           // 0..3 (64 cols)
    const int nt   = blockIdx.x;      // 0..3
    const int mt   = blockIdx.y;      // 0..511

    const uint4* gA = g_hA  + (size_t)mt * 16 * 512;
    const uint4* gB = g_w2p + (size_t)nt * 16 * 1024;

    float acc[4][8][4] = {};

    // prologue: chunk 0 -> stage 0
    {
        uint32_t dA = sbase + tid * 16;
        #pragma unroll
        for (int i = 0; i < 2; i++) cp16(dA + i * 4096, gA + tid + i * 256);
        uint32_t dB = sbase + CHUNK_A + tid * 16;
        #pragma unroll
        for (int i = 0; i < 4; i++) cp16(dB + i * 4096, gB + tid + i * 256);
        cp_commit();
    }

    for (int c = 0; c < 16; c++) {
        const int s = c & 1;
        if (c < 15) {
            const int sn = s ^ 1;
            uint32_t dA = sbase + sn * STAGE + tid * 16;
            const uint4* pA = gA + (c + 1) * 512 + tid;
            #pragma unroll
            for (int i = 0; i < 2; i++) cp16(dA + i * 4096, pA + i * 256);
            uint32_t dB = sbase + sn * STAGE + CHUNK_A + tid * 16;
            const uint4* pB = gB + (c + 1) * 1024 + tid;
            #pragma unroll
            for (int i = 0; i < 4; i++) cp16(dB + i * 4096, pB + i * 256);
            cp_commit();
            cp_wait<1>();
        } else {
            cp_wait<0>();
        }
        __syncthreads();

        const uint4* sA = (const uint4*)(smem + s * STAGE);
        const uint4* sB = (const uint4*)(smem + s * STAGE + CHUNK_A);

        uint4 bf[8];
        #pragma unroll
        for (int p = 0; p < 8; p++)
            bf[p] = sB[(wn * 8 + p) * 32 + lane];

        #pragma unroll
        for (int ks = 0; ks < 2; ks++) {
            uint4 af[4];
            #pragma unroll
            for (int mb = 0; mb < 4; mb++)
                af[mb] = sA[((wm * 4 + mb) * 2 + ks) * 32 + lane];
            #pragma unroll
            for (int mb = 0; mb < 4; mb++) {
                #pragma unroll
                for (int p = 0; p < 8; p++) {
                    uint32_t b0 = ks ? bf[p].z : bf[p].x;
                    uint32_t b1 = ks ? bf[p].w : bf[p].y;
                    mma_f16(acc[mb][p], af[mb].x, af[mb].y, af[mb].z, af[mb].w, b0, b1);
                }
            }
        }
        __syncthreads();
    }

    // epilogue: pairwise STG.64
    #pragma unroll
    for (int mb = 0; mb < 4; mb++) {
        size_t r = (size_t)mt * 128 + wm * 64 + mb * 16 + (lane >> 2);
        #pragma unroll
        for (int p = 0; p < 8; p++) {
            int cg = nt * 256 + wn * 64 + p * 8 + (lane & 3) * 2;
            *(float2*)(out + r * V_ + cg) =
                make_float2(acc[mb][p][0], acc[mb][p][1]);
            *(float2*)(out + (r + 8) * V_ + cg) =
                make_float2(acc[mb][p][2], acc[mb][p][3]);
        }
    }
}

extern "C" void kernel_launch(void* const* d_in, const int* in_sizes, int n_in,
                              void* d_out, int out_size) {
    const float* enc = (const float*)d_in[0];
    const float* dec = (const float*)d_in[1];
    const float* w1  = (const float*)d_in[2];
    const float* b1  = (const float*)d_in[3];
    const float* w2  = (const float*)d_in[4];
    float* out = (float*)d_out;

    cudaFuncSetAttribute(prep_kernel, cudaFuncAttributeMaxDynamicSharedMemorySize, P_SMEM);
    cudaFuncSetAttribute(gemm_kernel, cudaFuncAttributeMaxDynamicSharedMemorySize, SMEM_GEMM);
    prep_kernel<<<416, 256, P_SMEM>>>(enc, dec, w1, b1, w2);
    hidden_kernel<<<1024, 256>>>();
    gemm_kernel<<<dim3(4, 512), 256, SMEM_GEMM>>>(out);
}